// round 1
// baseline (speedup 1.0000x reference)
#include <cuda_runtime.h>
#include <math.h>

#define BATCH 4
#define CCH   256
#define NPIX  4096

// Scratch (allocation-free rule: __device__ globals)
__device__ float g_qT[BATCH * NPIX * CCH];                 // [b][n][c]
__device__ float g_kT[BATCH * NPIX * CCH];                 // [b][n][c]
__device__ float g_vT[BATCH * NPIX * CCH];                 // [b][n][c]
__device__ float g_energy[(size_t)BATCH * NPIX * NPIX];    // [b][i][j], softmaxed in place

// ---------------------------------------------------------------------------
// Kernel 1: qT/kT/vT[b][n][o] = sum_c W[o][c] * x[b][c][n] + bias[o]
// 64x64 tile, 256 threads, 4x4 per thread, K-chunk 16.
// blockIdx.z = b*3 + w  (w: 0=q, 1=k, 2=v)
// ---------------------------------------------------------------------------
__global__ __launch_bounds__(256) void qkv_kernel(
    const float* __restrict__ x,
    const float* __restrict__ Wq, const float* __restrict__ bq,
    const float* __restrict__ Wk, const float* __restrict__ bk,
    const float* __restrict__ Wv, const float* __restrict__ bv)
{
    const int bz = blockIdx.z;
    const int b  = bz / 3;
    const int w  = bz % 3;
    const float* W;
    const float* bias;
    float* dst;
    if (w == 0)      { W = Wq; bias = bq; dst = g_qT; }
    else if (w == 1) { W = Wk; bias = bk; dst = g_kT; }
    else             { W = Wv; bias = bv; dst = g_vT; }
    const float* xb = x + (size_t)b * CCH * NPIX;
    dst += (size_t)b * NPIX * CCH;

    const int n0 = blockIdx.x * 64;
    const int o0 = blockIdx.y * 64;

    __shared__ float As[16][64];  // x[c'][n']
    __shared__ float Bs[16][64];  // W  [c'][o']  (transposed on store)

    const int t  = threadIdx.x;
    const int tx = t & 15;        // o-frag
    const int ty = t >> 4;        // n-frag

    float acc[4][4];
#pragma unroll
    for (int i = 0; i < 4; i++)
#pragma unroll
        for (int j = 0; j < 4; j++) acc[i][j] = 0.f;

    for (int c0 = 0; c0 < CCH; c0 += 16) {
        // As: 16 c-rows x 64 n, contiguous in n
        {
            const int cp = t >> 4, n4 = t & 15;
            float4 v4 = *(const float4*)&xb[(size_t)(c0 + cp) * NPIX + n0 + 4 * n4];
            *(float4*)&As[cp][4 * n4] = v4;
        }
        // Bs: read W[o][c] rows (contiguous in c), store transposed [c'][o']
        {
            const int op = t >> 2, q = t & 3;
            float4 v4 = *(const float4*)&W[(size_t)(o0 + op) * CCH + c0 + 4 * q];
            Bs[4 * q + 0][op] = v4.x;
            Bs[4 * q + 1][op] = v4.y;
            Bs[4 * q + 2][op] = v4.z;
            Bs[4 * q + 3][op] = v4.w;
        }
        __syncthreads();
#pragma unroll
        for (int k = 0; k < 16; k++) {
            float4 a  = *(float4*)&As[k][4 * ty];
            float4 bb = *(float4*)&Bs[k][4 * tx];
            float av[4] = {a.x, a.y, a.z, a.w};
            float bw[4] = {bb.x, bb.y, bb.z, bb.w};
#pragma unroll
            for (int i = 0; i < 4; i++)
#pragma unroll
                for (int j = 0; j < 4; j++) acc[i][j] = fmaf(av[i], bw[j], acc[i][j]);
        }
        __syncthreads();
    }

    float4 b4 = *(const float4*)&bias[o0 + 4 * tx];
    const float bw[4] = {b4.x, b4.y, b4.z, b4.w};
#pragma unroll
    for (int i = 0; i < 4; i++) {
        const int n = n0 + 4 * ty + i;
        float4 o;
        o.x = acc[i][0] + bw[0];
        o.y = acc[i][1] + bw[1];
        o.z = acc[i][2] + bw[2];
        o.w = acc[i][3] + bw[3];
        *(float4*)&dst[(size_t)n * CCH + o0 + 4 * tx] = o;
    }
}

// ---------------------------------------------------------------------------
// Kernel 2: energy[b][i][j] = qT[b][i][:] . kT[b][j][:]
// 128x128 tile, 256 threads, 8x8 per thread (split 4+4), K-chunk 16.
// ---------------------------------------------------------------------------
__global__ __launch_bounds__(256) void energy_kernel()
{
    const int b  = blockIdx.z;
    const int i0 = blockIdx.y * 128;
    const int j0 = blockIdx.x * 128;

    const float* Q = g_qT + (size_t)b * NPIX * CCH;
    const float* K = g_kT + (size_t)b * NPIX * CCH;
    float* E = g_energy + (size_t)b * NPIX * NPIX;

    __shared__ float As[16][128];  // q [c'][i']
    __shared__ float Bs[16][128];  // k [c'][j']

    const int t  = threadIdx.x;
    const int tx = t & 15;  // j-frag
    const int ty = t >> 4;  // i-frag

    float acc[8][8];
#pragma unroll
    for (int i = 0; i < 8; i++)
#pragma unroll
        for (int j = 0; j < 8; j++) acc[i][j] = 0.f;

    for (int c0 = 0; c0 < CCH; c0 += 16) {
#pragma unroll
        for (int l = 0; l < 2; l++) {
            const int idx = t + l * 256;
            const int row = idx >> 2, q4 = idx & 3;
            float4 va = *(const float4*)&Q[(size_t)(i0 + row) * CCH + c0 + 4 * q4];
            As[4 * q4 + 0][row] = va.x;
            As[4 * q4 + 1][row] = va.y;
            As[4 * q4 + 2][row] = va.z;
            As[4 * q4 + 3][row] = va.w;
            float4 vb = *(const float4*)&K[(size_t)(j0 + row) * CCH + c0 + 4 * q4];
            Bs[4 * q4 + 0][row] = vb.x;
            Bs[4 * q4 + 1][row] = vb.y;
            Bs[4 * q4 + 2][row] = vb.z;
            Bs[4 * q4 + 3][row] = vb.w;
        }
        __syncthreads();
#pragma unroll
        for (int k = 0; k < 16; k++) {
            float4 a0 = *(float4*)&As[k][4 * ty];
            float4 a1 = *(float4*)&As[k][64 + 4 * ty];
            float4 b0 = *(float4*)&Bs[k][4 * tx];
            float4 b1 = *(float4*)&Bs[k][64 + 4 * tx];
            float av[8] = {a0.x, a0.y, a0.z, a0.w, a1.x, a1.y, a1.z, a1.w};
            float bw[8] = {b0.x, b0.y, b0.z, b0.w, b1.x, b1.y, b1.z, b1.w};
#pragma unroll
            for (int i = 0; i < 8; i++)
#pragma unroll
                for (int j = 0; j < 8; j++) acc[i][j] = fmaf(av[i], bw[j], acc[i][j]);
        }
        __syncthreads();
    }

#pragma unroll
    for (int ii = 0; ii < 8; ii++) {
        const int i = i0 + ((ii < 4) ? (4 * ty + ii) : (64 + 4 * ty + ii - 4));
        float4 o0v = make_float4(acc[ii][0], acc[ii][1], acc[ii][2], acc[ii][3]);
        float4 o1v = make_float4(acc[ii][4], acc[ii][5], acc[ii][6], acc[ii][7]);
        *(float4*)&E[(size_t)i * NPIX + j0 + 4 * tx]      = o0v;
        *(float4*)&E[(size_t)i * NPIX + j0 + 64 + 4 * tx] = o1v;
    }
}

// ---------------------------------------------------------------------------
// Kernel 3: in-place row softmax over 4096 columns. One block (256 thr) per row.
// ---------------------------------------------------------------------------
__global__ __launch_bounds__(256) void softmax_kernel()
{
    const size_t row = blockIdx.x;                 // 0 .. B*N-1
    float* p = g_energy + row * NPIX;
    const int t = threadIdx.x;

    __shared__ float red[8];

    float vals[16];
    float m = -INFINITY;
#pragma unroll
    for (int l = 0; l < 4; l++) {
        float4 v = *(const float4*)&p[4 * (t + 256 * l)];
        vals[4 * l + 0] = v.x; vals[4 * l + 1] = v.y;
        vals[4 * l + 2] = v.z; vals[4 * l + 3] = v.w;
        m = fmaxf(m, fmaxf(fmaxf(v.x, v.y), fmaxf(v.z, v.w)));
    }
#pragma unroll
    for (int s = 16; s > 0; s >>= 1) m = fmaxf(m, __shfl_xor_sync(0xffffffffu, m, s));
    if ((t & 31) == 0) red[t >> 5] = m;
    __syncthreads();
    m = red[t & 7];
#pragma unroll
    for (int s = 4; s > 0; s >>= 1) m = fmaxf(m, __shfl_xor_sync(0xffffffffu, m, s));

    float s = 0.f;
#pragma unroll
    for (int i = 0; i < 16; i++) {
        vals[i] = expf(vals[i] - m);
        s += vals[i];
    }
#pragma unroll
    for (int sh = 16; sh > 0; sh >>= 1) s += __shfl_xor_sync(0xffffffffu, s, sh);
    __syncthreads();
    if ((t & 31) == 0) red[t >> 5] = s;
    __syncthreads();
    s = red[t & 7];
#pragma unroll
    for (int sh = 4; sh > 0; sh >>= 1) s += __shfl_xor_sync(0xffffffffu, s, sh);

    const float inv = 1.f / s;
#pragma unroll
    for (int l = 0; l < 4; l++) {
        float4 v = make_float4(vals[4 * l + 0] * inv, vals[4 * l + 1] * inv,
                               vals[4 * l + 2] * inv, vals[4 * l + 3] * inv);
        *(float4*)&p[4 * (t + 256 * l)] = v;
    }
}

// ---------------------------------------------------------------------------
// Kernel 4: out[b][c][i] = gamma * sum_j attn[b][i][j] * vT[b][j][c] + x[b][c][i]
// Tile: 64 (i) x 128 (c), 256 threads, per-thread 4(i) x 8(c), K-chunk 16.
// i maps across tx so final stores are coalesced float4 in i.
// ---------------------------------------------------------------------------
__global__ __launch_bounds__(256) void av_kernel(
    const float* __restrict__ x, const float* __restrict__ gamma,
    float* __restrict__ out)
{
    const int b  = blockIdx.z;
    const int i0 = blockIdx.x * 64;
    const int c0 = blockIdx.y * 128;

    const float* A = g_energy + (size_t)b * NPIX * NPIX;  // attn [i][j]
    const float* V = g_vT + (size_t)b * NPIX * CCH;       // [j][c]

    __shared__ float As[16][64];   // attn [j'][i']
    __shared__ float Bs[16][128];  // v    [j'][c']

    const int t  = threadIdx.x;
    const int tx = t & 15;  // i-frag
    const int ty = t >> 4;  // c-frag

    float acc[8][4];
#pragma unroll
    for (int i = 0; i < 8; i++)
#pragma unroll
        for (int j = 0; j < 4; j++) acc[i][j] = 0.f;

    for (int j0 = 0; j0 < NPIX; j0 += 16) {
        // attn tile: 64 i rows x 16 j, contiguous in j, store transposed
        {
            const int r = t >> 2, q = t & 3;
            float4 v = *(const float4*)&A[(size_t)(i0 + r) * NPIX + j0 + 4 * q];
            As[4 * q + 0][r] = v.x;
            As[4 * q + 1][r] = v.y;
            As[4 * q + 2][r] = v.z;
            As[4 * q + 3][r] = v.w;
        }
        // v tile: 16 j rows x 128 c, contiguous in c, direct layout
        {
#pragma unroll
            for (int l = 0; l < 2; l++) {
                const int idx = t + l * 256;
                const int jp = idx >> 5, c4 = idx & 31;
                float4 v = *(const float4*)&V[(size_t)(j0 + jp) * CCH + c0 + 4 * c4];
                *(float4*)&Bs[jp][4 * c4] = v;
            }
        }
        __syncthreads();
#pragma unroll
        for (int k = 0; k < 16; k++) {
            float4 a  = *(float4*)&As[k][4 * tx];
            float4 b0 = *(float4*)&Bs[k][8 * ty];
            float4 b1 = *(float4*)&Bs[k][8 * ty + 4];
            float av[4] = {a.x, a.y, a.z, a.w};
            float bw[8] = {b0.x, b0.y, b0.z, b0.w, b1.x, b1.y, b1.z, b1.w};
#pragma unroll
            for (int cc = 0; cc < 8; cc++)
#pragma unroll
                for (int ii = 0; ii < 4; ii++)
                    acc[cc][ii] = fmaf(bw[cc], av[ii], acc[cc][ii]);
        }
        __syncthreads();
    }

    const float g = gamma[0];
#pragma unroll
    for (int cc = 0; cc < 8; cc++) {
        const int c = c0 + 8 * ty + cc;
        const size_t off = ((size_t)b * CCH + c) * NPIX + i0 + 4 * tx;
        float4 xv = *(const float4*)&x[off];
        float4 o;
        o.x = fmaf(g, acc[cc][0], xv.x);
        o.y = fmaf(g, acc[cc][1], xv.y);
        o.z = fmaf(g, acc[cc][2], xv.z);
        o.w = fmaf(g, acc[cc][3], xv.w);
        *(float4*)&out[off] = o;
    }
}

// ---------------------------------------------------------------------------
extern "C" void kernel_launch(void* const* d_in, const int* in_sizes, int n_in,
                              void* d_out, int out_size)
{
    const float* x     = (const float*)d_in[0];
    const float* Wq    = (const float*)d_in[1];
    const float* bq    = (const float*)d_in[2];
    const float* Wk    = (const float*)d_in[3];
    const float* bk    = (const float*)d_in[4];
    const float* Wv    = (const float*)d_in[5];
    const float* bv    = (const float*)d_in[6];
    const float* gamma = (const float*)d_in[7];
    float* out = (float*)d_out;

    // K1: QKV projections -> qT/kT/vT [B][N][C]
    {
        dim3 grid(NPIX / 64, CCH / 64, BATCH * 3);
        qkv_kernel<<<grid, 256>>>(x, Wq, bq, Wk, bk, Wv, bv);
    }
    // K2: energy = q . k  [B][N][N]
    {
        dim3 grid(NPIX / 128, NPIX / 128, BATCH);
        energy_kernel<<<grid, 256>>>();
    }
    // K3: row softmax in place
    {
        softmax_kernel<<<BATCH * NPIX, 256>>>();
    }
    // K4: out = gamma * (attn @ vT)^T + x
    {
        dim3 grid(NPIX / 64, CCH / 128, BATCH);
        av_kernel<<<grid, 256>>>(x, gamma, out);
    }
    (void)in_sizes; (void)n_in; (void)out_size;
}

// round 2
// speedup vs baseline: 1.0001x; 1.0001x over previous
#include <cuda_runtime.h>
#include <math.h>

#define BATCH 4
#define CCH   256
#define NPIX  4096

// Scratch (allocation-free rule: __device__ globals)
__device__ float g_qT[BATCH * NPIX * CCH];                 // [b][n][c]
__device__ float g_kT[BATCH * NPIX * CCH];                 // [b][n][c]
__device__ float g_vT[BATCH * NPIX * CCH];                 // [b][n][c]
__device__ float g_energy[(size_t)BATCH * NPIX * NPIX];    // [b][i][j], softmaxed in place

// ---------------------------------------------------------------------------
// Kernel 1: qT/kT/vT[b][n][o] = sum_c W[o][c] * x[b][c][n] + bias[o]
// 64x64 tile, 256 threads, 4x4 per thread, K-chunk 16.
// blockIdx.z = b*3 + w  (w: 0=q, 1=k, 2=v)
// ---------------------------------------------------------------------------
__global__ __launch_bounds__(256) void qkv_kernel(
    const float* __restrict__ x,
    const float* __restrict__ Wq, const float* __restrict__ bq,
    const float* __restrict__ Wk, const float* __restrict__ bk,
    const float* __restrict__ Wv, const float* __restrict__ bv)
{
    const int bz = blockIdx.z;
    const int b  = bz / 3;
    const int w  = bz % 3;
    const float* W;
    const float* bias;
    float* dst;
    if (w == 0)      { W = Wq; bias = bq; dst = g_qT; }
    else if (w == 1) { W = Wk; bias = bk; dst = g_kT; }
    else             { W = Wv; bias = bv; dst = g_vT; }
    const float* xb = x + (size_t)b * CCH * NPIX;
    dst += (size_t)b * NPIX * CCH;

    const int n0 = blockIdx.x * 64;
    const int o0 = blockIdx.y * 64;

    __shared__ float As[16][64];  // x[c'][n']
    __shared__ float Bs[16][64];  // W  [c'][o']  (transposed on store)

    const int t  = threadIdx.x;
    const int tx = t & 15;        // o-frag
    const int ty = t >> 4;        // n-frag

    float acc[4][4];
#pragma unroll
    for (int i = 0; i < 4; i++)
#pragma unroll
        for (int j = 0; j < 4; j++) acc[i][j] = 0.f;

    for (int c0 = 0; c0 < CCH; c0 += 16) {
        // As: 16 c-rows x 64 n, contiguous in n
        {
            const int cp = t >> 4, n4 = t & 15;
            float4 v4 = *(const float4*)&xb[(size_t)(c0 + cp) * NPIX + n0 + 4 * n4];
            *(float4*)&As[cp][4 * n4] = v4;
        }
        // Bs: read W[o][c] rows (contiguous in c), store transposed [c'][o']
        {
            const int op = t >> 2, q = t & 3;
            float4 v4 = *(const float4*)&W[(size_t)(o0 + op) * CCH + c0 + 4 * q];
            Bs[4 * q + 0][op] = v4.x;
            Bs[4 * q + 1][op] = v4.y;
            Bs[4 * q + 2][op] = v4.z;
            Bs[4 * q + 3][op] = v4.w;
        }
        __syncthreads();
#pragma unroll
        for (int k = 0; k < 16; k++) {
            float4 a  = *(float4*)&As[k][4 * ty];
            float4 bb = *(float4*)&Bs[k][4 * tx];
            float av[4] = {a.x, a.y, a.z, a.w};
            float bw[4] = {bb.x, bb.y, bb.z, bb.w};
#pragma unroll
            for (int i = 0; i < 4; i++)
#pragma unroll
                for (int j = 0; j < 4; j++) acc[i][j] = fmaf(av[i], bw[j], acc[i][j]);
        }
        __syncthreads();
    }

    float4 b4 = *(const float4*)&bias[o0 + 4 * tx];
    const float bw[4] = {b4.x, b4.y, b4.z, b4.w};
#pragma unroll
    for (int i = 0; i < 4; i++) {
        const int n = n0 + 4 * ty + i;
        float4 o;
        o.x = acc[i][0] + bw[0];
        o.y = acc[i][1] + bw[1];
        o.z = acc[i][2] + bw[2];
        o.w = acc[i][3] + bw[3];
        *(float4*)&dst[(size_t)n * CCH + o0 + 4 * tx] = o;
    }
}

// ---------------------------------------------------------------------------
// Kernel 2: energy[b][i][j] = qT[b][i][:] . kT[b][j][:]
// 128x128 tile, 256 threads, 8x8 per thread (split 4+4), K-chunk 16.
// ---------------------------------------------------------------------------
__global__ __launch_bounds__(256) void energy_kernel()
{
    const int b  = blockIdx.z;
    const int i0 = blockIdx.y * 128;
    const int j0 = blockIdx.x * 128;

    const float* Q = g_qT + (size_t)b * NPIX * CCH;
    const float* K = g_kT + (size_t)b * NPIX * CCH;
    float* E = g_energy + (size_t)b * NPIX * NPIX;

    __shared__ float As[16][128];  // q [c'][i']
    __shared__ float Bs[16][128];  // k [c'][j']

    const int t  = threadIdx.x;
    const int tx = t & 15;  // j-frag
    const int ty = t >> 4;  // i-frag

    float acc[8][8];
#pragma unroll
    for (int i = 0; i < 8; i++)
#pragma unroll
        for (int j = 0; j < 8; j++) acc[i][j] = 0.f;

    for (int c0 = 0; c0 < CCH; c0 += 16) {
#pragma unroll
        for (int l = 0; l < 2; l++) {
            const int idx = t + l * 256;
            const int row = idx >> 2, q4 = idx & 3;
            float4 va = *(const float4*)&Q[(size_t)(i0 + row) * CCH + c0 + 4 * q4];
            As[4 * q4 + 0][row] = va.x;
            As[4 * q4 + 1][row] = va.y;
            As[4 * q4 + 2][row] = va.z;
            As[4 * q4 + 3][row] = va.w;
            float4 vb = *(const float4*)&K[(size_t)(j0 + row) * CCH + c0 + 4 * q4];
            Bs[4 * q4 + 0][row] = vb.x;
            Bs[4 * q4 + 1][row] = vb.y;
            Bs[4 * q4 + 2][row] = vb.z;
            Bs[4 * q4 + 3][row] = vb.w;
        }
        __syncthreads();
#pragma unroll
        for (int k = 0; k < 16; k++) {
            float4 a0 = *(float4*)&As[k][4 * ty];
            float4 a1 = *(float4*)&As[k][64 + 4 * ty];
            float4 b0 = *(float4*)&Bs[k][4 * tx];
            float4 b1 = *(float4*)&Bs[k][64 + 4 * tx];
            float av[8] = {a0.x, a0.y, a0.z, a0.w, a1.x, a1.y, a1.z, a1.w};
            float bw[8] = {b0.x, b0.y, b0.z, b0.w, b1.x, b1.y, b1.z, b1.w};
#pragma unroll
            for (int i = 0; i < 8; i++)
#pragma unroll
                for (int j = 0; j < 8; j++) acc[i][j] = fmaf(av[i], bw[j], acc[i][j]);
        }
        __syncthreads();
    }

#pragma unroll
    for (int ii = 0; ii < 8; ii++) {
        const int i = i0 + ((ii < 4) ? (4 * ty + ii) : (64 + 4 * ty + ii - 4));
        float4 o0v = make_float4(acc[ii][0], acc[ii][1], acc[ii][2], acc[ii][3]);
        float4 o1v = make_float4(acc[ii][4], acc[ii][5], acc[ii][6], acc[ii][7]);
        *(float4*)&E[(size_t)i * NPIX + j0 + 4 * tx]      = o0v;
        *(float4*)&E[(size_t)i * NPIX + j0 + 64 + 4 * tx] = o1v;
    }
}

// ---------------------------------------------------------------------------
// Kernel 3: in-place row softmax over 4096 columns. One block (256 thr) per row.
// ---------------------------------------------------------------------------
__global__ __launch_bounds__(256) void softmax_kernel()
{
    const size_t row = blockIdx.x;                 // 0 .. B*N-1
    float* p = g_energy + row * NPIX;
    const int t = threadIdx.x;

    __shared__ float red[8];

    float vals[16];
    float m = -INFINITY;
#pragma unroll
    for (int l = 0; l < 4; l++) {
        float4 v = *(const float4*)&p[4 * (t + 256 * l)];
        vals[4 * l + 0] = v.x; vals[4 * l + 1] = v.y;
        vals[4 * l + 2] = v.z; vals[4 * l + 3] = v.w;
        m = fmaxf(m, fmaxf(fmaxf(v.x, v.y), fmaxf(v.z, v.w)));
    }
#pragma unroll
    for (int s = 16; s > 0; s >>= 1) m = fmaxf(m, __shfl_xor_sync(0xffffffffu, m, s));
    if ((t & 31) == 0) red[t >> 5] = m;
    __syncthreads();
    m = red[t & 7];
#pragma unroll
    for (int s = 4; s > 0; s >>= 1) m = fmaxf(m, __shfl_xor_sync(0xffffffffu, m, s));

    float s = 0.f;
#pragma unroll
    for (int i = 0; i < 16; i++) {
        vals[i] = expf(vals[i] - m);
        s += vals[i];
    }
#pragma unroll
    for (int sh = 16; sh > 0; sh >>= 1) s += __shfl_xor_sync(0xffffffffu, s, sh);
    __syncthreads();
    if ((t & 31) == 0) red[t >> 5] = s;
    __syncthreads();
    s = red[t & 7];
#pragma unroll
    for (int sh = 4; sh > 0; sh >>= 1) s += __shfl_xor_sync(0xffffffffu, s, sh);

    const float inv = 1.f / s;
#pragma unroll
    for (int l = 0; l < 4; l++) {
        float4 v = make_float4(vals[4 * l + 0] * inv, vals[4 * l + 1] * inv,
                               vals[4 * l + 2] * inv, vals[4 * l + 3] * inv);
        *(float4*)&p[4 * (t + 256 * l)] = v;
    }
}

// ---------------------------------------------------------------------------
// Kernel 4: out[b][c][i] = gamma * sum_j attn[b][i][j] * vT[b][j][c] + x[b][c][i]
// Tile: 64 (i) x 128 (c), 256 threads, per-thread 4(i) x 8(c), K-chunk 16.
// i maps across tx so final stores are coalesced float4 in i.
// ---------------------------------------------------------------------------
__global__ __launch_bounds__(256) void av_kernel(
    const float* __restrict__ x, const float* __restrict__ gamma,
    float* __restrict__ out)
{
    const int b  = blockIdx.z;
    const int i0 = blockIdx.x * 64;
    const int c0 = blockIdx.y * 128;

    const float* A = g_energy + (size_t)b * NPIX * NPIX;  // attn [i][j]
    const float* V = g_vT + (size_t)b * NPIX * CCH;       // [j][c]

    __shared__ float As[16][64];   // attn [j'][i']
    __shared__ float Bs[16][128];  // v    [j'][c']

    const int t  = threadIdx.x;
    const int tx = t & 15;  // i-frag
    const int ty = t >> 4;  // c-frag

    float acc[8][4];
#pragma unroll
    for (int i = 0; i < 8; i++)
#pragma unroll
        for (int j = 0; j < 4; j++) acc[i][j] = 0.f;

    for (int j0 = 0; j0 < NPIX; j0 += 16) {
        // attn tile: 64 i rows x 16 j, contiguous in j, store transposed
        {
            const int r = t >> 2, q = t & 3;
            float4 v = *(const float4*)&A[(size_t)(i0 + r) * NPIX + j0 + 4 * q];
            As[4 * q + 0][r] = v.x;
            As[4 * q + 1][r] = v.y;
            As[4 * q + 2][r] = v.z;
            As[4 * q + 3][r] = v.w;
        }
        // v tile: 16 j rows x 128 c, contiguous in c, direct layout
        {
#pragma unroll
            for (int l = 0; l < 2; l++) {
                const int idx = t + l * 256;
                const int jp = idx >> 5, c4 = idx & 31;
                float4 v = *(const float4*)&V[(size_t)(j0 + jp) * CCH + c0 + 4 * c4];
                *(float4*)&Bs[jp][4 * c4] = v;
            }
        }
        __syncthreads();
#pragma unroll
        for (int k = 0; k < 16; k++) {
            float4 a  = *(float4*)&As[k][4 * tx];
            float4 b0 = *(float4*)&Bs[k][8 * ty];
            float4 b1 = *(float4*)&Bs[k][8 * ty + 4];
            float av[4] = {a.x, a.y, a.z, a.w};
            float bw[8] = {b0.x, b0.y, b0.z, b0.w, b1.x, b1.y, b1.z, b1.w};
#pragma unroll
            for (int cc = 0; cc < 8; cc++)
#pragma unroll
                for (int ii = 0; ii < 4; ii++)
                    acc[cc][ii] = fmaf(bw[cc], av[ii], acc[cc][ii]);
        }
        __syncthreads();
    }

    const float g = gamma[0];
#pragma unroll
    for (int cc = 0; cc < 8; cc++) {
        const int c = c0 + 8 * ty + cc;
        const size_t off = ((size_t)b * CCH + c) * NPIX + i0 + 4 * tx;
        float4 xv = *(const float4*)&x[off];
        float4 o;
        o.x = fmaf(g, acc[cc][0], xv.x);
        o.y = fmaf(g, acc[cc][1], xv.y);
        o.z = fmaf(g, acc[cc][2], xv.z);
        o.w = fmaf(g, acc[cc][3], xv.w);
        *(float4*)&out[off] = o;
    }
}

// ---------------------------------------------------------------------------
extern "C" void kernel_launch(void* const* d_in, const int* in_sizes, int n_in,
                              void* d_out, int out_size)
{
    const float* x     = (const float*)d_in[0];
    const float* Wq    = (const float*)d_in[1];
    const float* bq    = (const float*)d_in[2];
    const float* Wk    = (const float*)d_in[3];
    const float* bk    = (const float*)d_in[4];
    const float* Wv    = (const float*)d_in[5];
    const float* bv    = (const float*)d_in[6];
    const float* gamma = (const float*)d_in[7];
    float* out = (float*)d_out;

    // K1: QKV projections -> qT/kT/vT [B][N][C]
    {
        dim3 grid(NPIX / 64, CCH / 64, BATCH * 3);
        qkv_kernel<<<grid, 256>>>(x, Wq, bq, Wk, bk, Wv, bv);
    }
    // K2: energy = q . k  [B][N][N]
    {
        dim3 grid(NPIX / 128, NPIX / 128, BATCH);
        energy_kernel<<<grid, 256>>>();
    }
    // K3: row softmax in place
    {
        softmax_kernel<<<BATCH * NPIX, 256>>>();
    }
    // K4: out = gamma * (attn @ vT)^T + x
    {
        dim3 grid(NPIX / 64, CCH / 128, BATCH);
        av_kernel<<<grid, 256>>>(x, gamma, out);
    }
    (void)in_sizes; (void)n_in; (void)out_size;
}